// round 1
// baseline (speedup 1.0000x reference)
#include <cuda_runtime.h>

// Problem constants (fixed by the dataset)
#define S_LEN  512      // sequence length (after transpose)
#define BATCH  1024     // batch
#define DIN    5        // input features
#define HID    128      // hidden size
#define GATES  512      // 4*HID
#define NBLK   128      // blocks (each owns BPB batch rows)
#define NTHR   256      // threads per block
#define BPB    8        // batch rows per block
#define NG1    32       // K groups (of 4) for layer-0 recurrence (K=128)
#define NG2    64       // K groups for layer-1 (K=256 = [h2 ; h1])
#define NCACHE 24       // weight k-groups cached in smem (24*8KB = 192KB)

#define SMEM_BYTES ((NCACHE*GATES*4 + 4*BPB*HID) * 4)  // weights + 2x h buf + 2x h1 stage

// ---------------- global scratch (static: no allocation) ----------------
__device__ float g_P1[NG1 * GATES * 4];      // packed w_hh0: [kk][col(=q*128+j)][4]
__device__ float g_P2[NG2 * GATES * 4];      // packed [w_hh1 ; w_ih1]
__device__ float g_h1[(size_t)NBLK * S_LEN * BPB * HID];   // layer-1 inputs, [blk][t][b][j]

// ---------------- helpers ----------------
__device__ __forceinline__ float sigf(float x) {
    return __fdividef(1.0f, 1.0f + __expf(-x));
}
__device__ __forceinline__ float tanhf_fast(float x) {
    float e = __expf(2.0f * x);                 // |x| bounded (~<=25) by weight init, no overflow issue;
    return 1.0f - __fdividef(2.0f, e + 1.0f);   // e=inf -> returns 1 exactly, e->0 -> -1. Accurate ~1e-7.
}

__device__ __forceinline__ void accum_group(float acc[4][4], const float4 w[4], const float4 hv[4]) {
#pragma unroll
    for (int q = 0; q < 4; q++) {
#pragma unroll
        for (int ib = 0; ib < 4; ib++) {
            acc[q][ib] = fmaf(w[q].x, hv[ib].x, acc[q][ib]);
            acc[q][ib] = fmaf(w[q].y, hv[ib].y, acc[q][ib]);
            acc[q][ib] = fmaf(w[q].z, hv[ib].z, acc[q][ib]);
            acc[q][ib] = fmaf(w[q].w, hv[ib].w, acc[q][ib]);
        }
    }
}

// ---------------- prologue: pack weights into coalesced float4 layout ----------------
// P[kk][col][dk] = W[col][4*kk+dk]   (col = gate*128 + j)
__global__ void pack_kernel(const float* __restrict__ whh0,
                            const float* __restrict__ whh1,
                            const float* __restrict__ wih1) {
    int i = blockIdx.x * blockDim.x + threadIdx.x;
    if (i >= GATES * HID) return;
    int col = i / HID;
    int k   = i % HID;
    int kk = k >> 2, dk = k & 3;
    g_P1[((size_t)kk * GATES + col) * 4 + dk]          = whh0[col * HID + k];
    g_P2[((size_t)kk * GATES + col) * 4 + dk]          = whh1[col * HID + k];
    g_P2[((size_t)(kk + NG1) * GATES + col) * 4 + dk]  = wih1[col * HID + k];
}

// ---------------- main persistent kernel ----------------
__global__ void __launch_bounds__(NTHR, 1) lstm_persistent(
    const float* __restrict__ x,
    const float* __restrict__ wih0,
    const float* __restrict__ bih0,
    const float* __restrict__ bhh0,
    const float* __restrict__ bih1,
    const float* __restrict__ bhh1,
    const float* __restrict__ fcw,
    const float* __restrict__ fcb,
    float* __restrict__ out)
{
    extern __shared__ float sm[];
    float* Wc   = sm;                          // NCACHE*GATES float4s of weights
    float* Hh   = sm + NCACHE * GATES * 4;     // 2 x [BPB][HID] h double buffer
    float* Hstg = Hh + 2 * BPB * HID;          // 2 x [BPB][HID] staged h1 (phase 2)

    const int tid = threadIdx.x;
    const int j   = tid & (HID - 1);   // hidden index
    const int bq  = tid >> 7;          // 0/1 : batch quadrant
    const int b0  = bq * 4;            // local batch base (4 rows per thread)
    const int blk = blockIdx.x;
    const int bg0 = blk * BPB;         // global batch base

    // per-thread constants: biases and w_ih0 rows (tiny K=5)
    float bias0[4], bias1[4], wih[4][DIN];
#pragma unroll
    for (int q = 0; q < 4; q++) {
        int r = q * HID + j;
        bias0[q] = __ldg(bih0 + r) + __ldg(bhh0 + r);
        bias1[q] = __ldg(bih1 + r) + __ldg(bhh1 + r);
#pragma unroll
        for (int d = 0; d < DIN; d++) wih[q][d] = __ldg(wih0 + r * DIN + d);
    }

    // zero h buffer 0 (h_0 = 0) and load phase-1 cached weights
    for (int i = tid; i < BPB * HID; i += NTHR) Hh[i] = 0.f;
    {
        const float4* src = (const float4*)g_P1;
        float4*       dst = (float4*)Wc;
        for (int i = tid; i < NCACHE * GATES; i += NTHR) dst[i] = src[i];
    }
    __syncthreads();

    float c[4] = {0.f, 0.f, 0.f, 0.f};

    // =================== phase 1: layer 0 ===================
    for (int t = 0; t < S_LEN; t++) {
        const int rb = t & 1, wb = rb ^ 1;
        const float4* Hr = (const float4*)(Hh + rb * BPB * HID);

        // input x loads issued early (used after the K loop)
        float xv[4][DIN];
#pragma unroll
        for (int ib = 0; ib < 4; ib++) {
            const float* xp = x + ((size_t)(bg0 + b0 + ib) * S_LEN + t) * DIN;
#pragma unroll
            for (int d = 0; d < DIN; d++) xv[ib][d] = __ldg(xp + d);
        }

        float acc[4][4];
#pragma unroll
        for (int q = 0; q < 4; q++)
#pragma unroll
            for (int ib = 0; ib < 4; ib++) acc[q][ib] = bias0[q];

        // cached weight groups (smem)
        const float4* WcF = (const float4*)Wc;
#pragma unroll 2
        for (int kk = 0; kk < NCACHE; kk++) {
            float4 w[4], hv[4];
#pragma unroll
            for (int q = 0; q < 4; q++) w[q] = WcF[kk * GATES + q * HID + j];
#pragma unroll
            for (int ib = 0; ib < 4; ib++) hv[ib] = Hr[(b0 + ib) * (HID / 4) + kk];
            accum_group(acc, w, hv);
        }
        // streamed weight groups (L2)
        {
            const float4* Pg = (const float4*)g_P1;
#pragma unroll
            for (int kk = NCACHE; kk < NG1; kk++) {
                float4 w[4], hv[4];
#pragma unroll
                for (int q = 0; q < 4; q++) w[q] = __ldg(&Pg[kk * GATES + q * HID + j]);
#pragma unroll
                for (int ib = 0; ib < 4; ib++) hv[ib] = Hr[(b0 + ib) * (HID / 4) + kk];
                accum_group(acc, w, hv);
            }
        }
        // input contribution (K=5)
#pragma unroll
        for (int q = 0; q < 4; q++)
#pragma unroll
            for (int ib = 0; ib < 4; ib++)
#pragma unroll
                for (int d = 0; d < DIN; d++)
                    acc[q][ib] = fmaf(wih[q][d], xv[ib][d], acc[q][ib]);

        // nonlinearity + state update; write h to smem (double buf) and h1 to global
        float* Hw  = Hh + wb * BPB * HID;
        float* h1p = g_h1 + (size_t)(blk * S_LEN + t) * BPB * HID;
#pragma unroll
        for (int ib = 0; ib < 4; ib++) {
            float ig = sigf(acc[0][ib]);
            float fg = sigf(acc[1][ib]);
            float gg = tanhf_fast(acc[2][ib]);
            float og = sigf(acc[3][ib]);
            c[ib] = fg * c[ib] + ig * gg;
            float h = og * tanhf_fast(c[ib]);
            Hw[(b0 + ib) * HID + j]  = h;
            h1p[(b0 + ib) * HID + j] = h;
        }
        __syncthreads();
    }

    // =================== phase 2 setup ===================
#pragma unroll
    for (int ib = 0; ib < 4; ib++) c[ib] = 0.f;
    {
        const float4* src = (const float4*)g_P2;
        float4*       dst = (float4*)Wc;
        for (int i = tid; i < NCACHE * GATES; i += NTHR) dst[i] = src[i];
    }
    for (int i = tid; i < BPB * HID; i += NTHR) Hh[i] = 0.f;     // h2_0 = 0
    // stage h1_0
    ((float4*)Hstg)[tid] =
        __ldg((const float4*)(g_h1 + (size_t)(blk * S_LEN + 0) * BPB * HID) + tid);
    __syncthreads();

    // =================== phase 2: layer 1 (K = 256) ===================
    for (int t = 0; t < S_LEN; t++) {
        const int rb = t & 1, wb = rb ^ 1;
        const float4* Hr = (const float4*)(Hh   + rb * BPB * HID);
        const float4* Hs = (const float4*)(Hstg + rb * BPB * HID);

        // prefetch next step's h1 (stored to smem at end of step)
        int tn = (t + 1 < S_LEN) ? (t + 1) : (S_LEN - 1);
        float4 stg = __ldg((const float4*)(g_h1 + (size_t)(blk * S_LEN + tn) * BPB * HID) + tid);

        float acc[4][4];
#pragma unroll
        for (int q = 0; q < 4; q++)
#pragma unroll
            for (int ib = 0; ib < 4; ib++) acc[q][ib] = bias1[q];

        const float4* WcF = (const float4*)Wc;
        const float4* Pg  = (const float4*)g_P2;
        // cached groups: all use h2 (kk < 32 and NCACHE <= 32)
#pragma unroll 2
        for (int kk = 0; kk < NCACHE; kk++) {
            float4 w[4], hv[4];
#pragma unroll
            for (int q = 0; q < 4; q++) w[q] = WcF[kk * GATES + q * HID + j];
#pragma unroll
            for (int ib = 0; ib < 4; ib++) hv[ib] = Hr[(b0 + ib) * (HID / 4) + kk];
            accum_group(acc, w, hv);
        }
        // streamed, still vs h2
#pragma unroll
        for (int kk = NCACHE; kk < NG1; kk++) {
            float4 w[4], hv[4];
#pragma unroll
            for (int q = 0; q < 4; q++) w[q] = __ldg(&Pg[kk * GATES + q * HID + j]);
#pragma unroll
            for (int ib = 0; ib < 4; ib++) hv[ib] = Hr[(b0 + ib) * (HID / 4) + kk];
            accum_group(acc, w, hv);
        }
        // streamed, vs staged h1_t
#pragma unroll 2
        for (int kk = NG1; kk < NG2; kk++) {
            float4 w[4], hv[4];
#pragma unroll
            for (int q = 0; q < 4; q++) w[q] = __ldg(&Pg[kk * GATES + q * HID + j]);
#pragma unroll
            for (int ib = 0; ib < 4; ib++) hv[ib] = Hs[(b0 + ib) * (HID / 4) + (kk - NG1)];
            accum_group(acc, w, hv);
        }

        float* Hw = Hh + wb * BPB * HID;
#pragma unroll
        for (int ib = 0; ib < 4; ib++) {
            float ig = sigf(acc[0][ib]);
            float fg = sigf(acc[1][ib]);
            float gg = tanhf_fast(acc[2][ib]);
            float og = sigf(acc[3][ib]);
            c[ib] = fg * c[ib] + ig * gg;
            float h = og * tanhf_fast(c[ib]);
            Hw[(b0 + ib) * HID + j] = h;
        }
        ((float4*)(Hstg + wb * BPB * HID))[tid] = stg;   // publish staged h1_{t+1}
        __syncthreads();
    }

    // =================== output: out[b] = h2_last[b] . fc_w + fc_b ===================
    const float* hfin = Hh + (S_LEN & 1) * BPB * HID;    // last write went to buffer 0
    int w = tid >> 5, lane = tid & 31;
    if (w < BPB) {
        float s = 0.f;
#pragma unroll
        for (int m = 0; m < HID; m += 32)
            s += hfin[w * HID + lane + m] * __ldg(fcw + lane + m);
#pragma unroll
        for (int o = 16; o > 0; o >>= 1) s += __shfl_down_sync(0xffffffffu, s, o);
        if (lane == 0) out[bg0 + w] = s + __ldg(fcb);
    }
}

// ---------------- launch ----------------
extern "C" void kernel_launch(void* const* d_in, const int* in_sizes, int n_in,
                              void* d_out, int out_size) {
    const float* x    = (const float*)d_in[0];
    const float* wih0 = (const float*)d_in[1];
    const float* whh0 = (const float*)d_in[2];
    const float* bih0 = (const float*)d_in[3];
    const float* bhh0 = (const float*)d_in[4];
    const float* wih1 = (const float*)d_in[5];
    const float* whh1 = (const float*)d_in[6];
    const float* bih1 = (const float*)d_in[7];
    const float* bhh1 = (const float*)d_in[8];
    const float* fcw  = (const float*)d_in[9];
    const float* fcb  = (const float*)d_in[10];
    float* out = (float*)d_out;

    (void)in_sizes; (void)n_in; (void)out_size;

    cudaFuncSetAttribute(lstm_persistent,
                         cudaFuncAttributeMaxDynamicSharedMemorySize, SMEM_BYTES);

    pack_kernel<<<(GATES * HID + 255) / 256, 256>>>(whh0, whh1, wih1);
    lstm_persistent<<<NBLK, NTHR, SMEM_BYTES>>>(x, wih0, bih0, bhh0,
                                                bih1, bhh1, fcw, fcb, out);
}

// round 2
// speedup vs baseline: 1.0819x; 1.0819x over previous
#include <cuda_runtime.h>

// Problem constants
#define S_LEN  512
#define DIN    5
#define HID    128
#define GATES  512
#define NBLK   128
#define NTHR   256
#define BPB    8      // batch rows per block
#define NG1    32     // K groups (of 4) layer-0 recurrence (K=128)
#define NG2    64     // K groups layer-1 (K=256 = [h2 ; h1])
#define NCACHE 25     // weight k-groups cached in smem (25*8KB = 200KB)

// smem layout (float offsets)
#define OFF_WC   0
#define WC_FLOATS (NCACHE*GATES*4)              // 51200
#define OFF_HH   WC_FLOATS                      // 2 x [8][128] h double buffer
#define OFF_HS   (OFF_HH + 2*BPB*HID)           // 2 x [8][128] staged h1
#define OFF_X    (OFF_HS + 2*BPB*HID)           // [8][2][128] gate exchange
#define SMEM_FLOATS (OFF_X + BPB*2*HID)         // 57344
#define SMEM_BYTES (SMEM_FLOATS*4)              // 229376 B

// ---------------- global scratch ----------------
__device__ __align__(16) float g_P1[NG1 * GATES * 4];
__device__ __align__(16) float g_P2[NG2 * GATES * 4];
__device__ __align__(16) float g_h1[(size_t)NBLK * S_LEN * BPB * HID];

// ---------------- helpers ----------------
typedef unsigned long long u64;

__device__ __forceinline__ void ffma2(u64 &d, u64 a, u64 b) {
    asm("fma.rn.f32x2 %0, %1, %2, %0;" : "+l"(d) : "l"(a), "l"(b));
}
__device__ __forceinline__ float flo(u64 v) { return __uint_as_float((unsigned)v); }
__device__ __forceinline__ float fhi(u64 v) { return __uint_as_float((unsigned)(v >> 32)); }

__device__ __forceinline__ float sigf(float x) {
    return __fdividef(1.0f, 1.0f + __expf(-x));
}
__device__ __forceinline__ float tanhf_fast(float x) {
    float e = __expf(2.0f * x);
    return 1.0f - __fdividef(2.0f, e + 1.0f);
}

// ---------------- prologue: pack weights ----------------
// P[kk][col][dk] = W[col][4*kk+dk]   (col = gate*128 + j)
__global__ void pack_kernel(const float* __restrict__ whh0,
                            const float* __restrict__ whh1,
                            const float* __restrict__ wih1) {
    int i = blockIdx.x * blockDim.x + threadIdx.x;
    if (i >= GATES * HID) return;
    int col = i / HID;
    int k   = i % HID;
    int kk = k >> 2, dk = k & 3;
    g_P1[((size_t)kk * GATES + col) * 4 + dk]          = whh0[col * HID + k];
    g_P2[((size_t)kk * GATES + col) * 4 + dk]          = whh1[col * HID + k];
    g_P2[((size_t)(kk + NG1) * GATES + col) * 4 + dk]  = wih1[col * HID + k];
}

// ---------------- main persistent kernel ----------------
// Thread (j, gp): gp=0 owns gates {i,f}, gp=1 owns gates {g,o}; 8 batch rows each.
__global__ void __launch_bounds__(NTHR, 1) lstm_persistent(
    const float* __restrict__ x,
    const float* __restrict__ wih0,
    const float* __restrict__ bih0,
    const float* __restrict__ bhh0,
    const float* __restrict__ bih1,
    const float* __restrict__ bhh1,
    const float* __restrict__ fcw,
    const float* __restrict__ fcb,
    float* __restrict__ out)
{
    extern __shared__ float sm[];
    float* Xex = sm + OFF_X;

    const int tid  = threadIdx.x;
    const int j    = tid & (HID - 1);
    const int gp   = tid >> 7;              // 0 or 1
    const int col0 = (2 * gp) * HID + j;    // weight column for my first gate
    const int col1 = col0 + HID;
    const int blk  = blockIdx.x;
    const int bg0  = blk * BPB;

    // biases + w_ih0 rows for my 2 gates
    float bias0[2], bias1[2], wih[2][DIN];
#pragma unroll
    for (int q = 0; q < 2; q++) {
        int r = (2 * gp + q) * HID + j;
        bias0[q] = __ldg(bih0 + r) + __ldg(bhh0 + r);
        bias1[q] = __ldg(bih1 + r) + __ldg(bhh1 + r);
#pragma unroll
        for (int d = 0; d < DIN; d++) wih[q][d] = __ldg(wih0 + r * DIN + d);
    }

    // zero h buffer 0, load phase-1 cached weights
    for (int i = tid; i < BPB * HID; i += NTHR) sm[OFF_HH + i] = 0.f;
    {
        const float4* src = (const float4*)g_P1;
        float4*       dst = (float4*)(sm + OFF_WC);
        for (int i = tid; i < NCACHE * GATES; i += NTHR) dst[i] = src[i];
    }
    __syncthreads();

    // c state: 4 rows per thread (gp=0 -> rows 0..3, gp=1 -> rows 4..7)
    float c[4] = {0.f, 0.f, 0.f, 0.f};
    const int mb = gp * 4;          // rows I finalize
    const int ob = (gp ^ 1) * 4;    // rows whose gates I export

    const ulonglong2* WcD = (const ulonglong2*)(sm + OFF_WC);
    const ulonglong2* P1D = (const ulonglong2*)g_P1;
    const ulonglong2* P2D = (const ulonglong2*)g_P2;

    // =================== phase 1: layer 0 ===================
    for (int t = 0; t < S_LEN; t++) {
        const int rb = t & 1, wb = rb ^ 1;
        const ulonglong2* HrD = (const ulonglong2*)(sm + OFF_HH + rb * BPB * HID);

        // prefetch streamed weights (groups NCACHE..NG1-1) early
        ulonglong2 ws0[NG1 - NCACHE], ws1[NG1 - NCACHE];
#pragma unroll
        for (int s = 0; s < NG1 - NCACHE; s++) {
            ws0[s] = __ldg(&P1D[(NCACHE + s) * GATES + col0]);
            ws1[s] = __ldg(&P1D[(NCACHE + s) * GATES + col1]);
        }

        // x loads early (all 8 rows, 5 features)
        float xv[BPB][DIN];
#pragma unroll
        for (int b = 0; b < BPB; b++) {
            const float* xp = x + ((size_t)(bg0 + b) * S_LEN + t) * DIN;
#pragma unroll
            for (int d = 0; d < DIN; d++) xv[b][d] = __ldg(xp + d);
        }

        u64 a0[BPB], a1[BPB];
#pragma unroll
        for (int b = 0; b < BPB; b++) { a0[b] = 0ull; a1[b] = 0ull; }

        // cached weight groups (smem)
#pragma unroll 5
        for (int kk = 0; kk < NCACHE; kk++) {
            ulonglong2 w0 = WcD[kk * GATES + col0];
            ulonglong2 w1 = WcD[kk * GATES + col1];
#pragma unroll
            for (int b = 0; b < BPB; b++) {
                ulonglong2 hv = HrD[b * 32 + kk];
                ffma2(a0[b], w0.x, hv.x);
                ffma2(a0[b], w0.y, hv.y);
                ffma2(a1[b], w1.x, hv.x);
                ffma2(a1[b], w1.y, hv.y);
            }
        }
        // streamed weight groups (already in regs)
#pragma unroll
        for (int s = 0; s < NG1 - NCACHE; s++) {
            int kk = NCACHE + s;
#pragma unroll
            for (int b = 0; b < BPB; b++) {
                ulonglong2 hv = HrD[b * 32 + kk];
                ffma2(a0[b], ws0[s].x, hv.x);
                ffma2(a0[b], ws0[s].y, hv.y);
                ffma2(a1[b], ws1[s].x, hv.x);
                ffma2(a1[b], ws1[s].y, hv.y);
            }
        }

        // finalize gate pre-activations (+ bias + x contribution)
        float g0[BPB], g1[BPB];
#pragma unroll
        for (int b = 0; b < BPB; b++) {
            float s0 = flo(a0[b]) + fhi(a0[b]) + bias0[0];
            float s1 = flo(a1[b]) + fhi(a1[b]) + bias0[1];
#pragma unroll
            for (int d = 0; d < DIN; d++) {
                s0 = fmaf(wih[0][d], xv[b][d], s0);
                s1 = fmaf(wih[1][d], xv[b][d], s1);
            }
            g0[b] = s0; g1[b] = s1;
        }

        // export gates for the rows the other half finalizes
#pragma unroll
        for (int r = 0; r < 4; r++) {
            int b = ob + r;
            Xex[b * 2 * HID + 0 * HID + j] = g0[b];
            Xex[b * 2 * HID + 1 * HID + j] = g1[b];
        }
        __syncthreads();

        // finalize my rows
        float* Hw  = sm + OFF_HH + wb * BPB * HID;
        float* h1p = g_h1 + (size_t)(blk * S_LEN + t) * BPB * HID;
#pragma unroll
        for (int r = 0; r < 4; r++) {
            int b = mb + r;
            float A = Xex[b * 2 * HID + 0 * HID + j];
            float B = Xex[b * 2 * HID + 1 * HID + j];
            float iv, fv, gv, ov;
            if (gp == 0) { iv = g0[b]; fv = g1[b]; gv = A; ov = B; }
            else         { gv = g0[b]; ov = g1[b]; iv = A; fv = B; }
            c[r] = sigf(fv) * c[r] + sigf(iv) * tanhf_fast(gv);
            float h = sigf(ov) * tanhf_fast(c[r]);
            Hw[b * HID + j]  = h;
            h1p[b * HID + j] = h;
        }
        __syncthreads();
    }

    // =================== phase 2 setup ===================
#pragma unroll
    for (int r = 0; r < 4; r++) c[r] = 0.f;
    {
        const float4* src = (const float4*)g_P2;
        float4*       dst = (float4*)(sm + OFF_WC);
        for (int i = tid; i < NCACHE * GATES; i += NTHR) dst[i] = src[i];
    }
    for (int i = tid; i < BPB * HID; i += NTHR) sm[OFF_HH + i] = 0.f;  // h2_0 = 0
    ((float4*)(sm + OFF_HS))[tid] =
        __ldg((const float4*)(g_h1 + (size_t)(blk * S_LEN + 0) * BPB * HID) + tid);
    __syncthreads();

    // =================== phase 2: layer 1 (K = 256) ===================
    for (int t = 0; t < S_LEN; t++) {
        const int rb = t & 1, wb = rb ^ 1;
        const ulonglong2* HrD = (const ulonglong2*)(sm + OFF_HH + rb * BPB * HID);
        const ulonglong2* HsD = (const ulonglong2*)(sm + OFF_HS + rb * BPB * HID);

        // prefetch next step's h1
        int tn = (t + 1 < S_LEN) ? (t + 1) : (S_LEN - 1);
        float4 stg = __ldg((const float4*)(g_h1 + (size_t)(blk * S_LEN + tn) * BPB * HID) + tid);

        u64 a0[BPB], a1[BPB];
#pragma unroll
        for (int b = 0; b < BPB; b++) { a0[b] = 0ull; a1[b] = 0ull; }

        // cached groups (h2 recurrence part, kk < NCACHE <= 32)
#pragma unroll 5
        for (int kk = 0; kk < NCACHE; kk++) {
            ulonglong2 w0 = WcD[kk * GATES + col0];
            ulonglong2 w1 = WcD[kk * GATES + col1];
#pragma unroll
            for (int b = 0; b < BPB; b++) {
                ulonglong2 hv = HrD[b * 32 + kk];
                ffma2(a0[b], w0.x, hv.x);
                ffma2(a0[b], w0.y, hv.y);
                ffma2(a1[b], w1.x, hv.x);
                ffma2(a1[b], w1.y, hv.y);
            }
        }
        // streamed vs h2
#pragma unroll 4
        for (int kk = NCACHE; kk < NG1; kk++) {
            ulonglong2 w0 = __ldg(&P2D[kk * GATES + col0]);
            ulonglong2 w1 = __ldg(&P2D[kk * GATES + col1]);
#pragma unroll
            for (int b = 0; b < BPB; b++) {
                ulonglong2 hv = HrD[b * 32 + kk];
                ffma2(a0[b], w0.x, hv.x);
                ffma2(a0[b], w0.y, hv.y);
                ffma2(a1[b], w1.x, hv.x);
                ffma2(a1[b], w1.y, hv.y);
            }
        }
        // streamed vs staged h1_t
#pragma unroll 4
        for (int kk = NG1; kk < NG2; kk++) {
            ulonglong2 w0 = __ldg(&P2D[kk * GATES + col0]);
            ulonglong2 w1 = __ldg(&P2D[kk * GATES + col1]);
#pragma unroll
            for (int b = 0; b < BPB; b++) {
                ulonglong2 hv = HsD[b * 32 + (kk - NG1)];
                ffma2(a0[b], w0.x, hv.x);
                ffma2(a0[b], w0.y, hv.y);
                ffma2(a1[b], w1.x, hv.x);
                ffma2(a1[b], w1.y, hv.y);
            }
        }

        float g0[BPB], g1[BPB];
#pragma unroll
        for (int b = 0; b < BPB; b++) {
            g0[b] = flo(a0[b]) + fhi(a0[b]) + bias1[0];
            g1[b] = flo(a1[b]) + fhi(a1[b]) + bias1[1];
        }

#pragma unroll
        for (int r = 0; r < 4; r++) {
            int b = ob + r;
            Xex[b * 2 * HID + 0 * HID + j] = g0[b];
            Xex[b * 2 * HID + 1 * HID + j] = g1[b];
        }
        __syncthreads();

        float* Hw = sm + OFF_HH + wb * BPB * HID;
#pragma unroll
        for (int r = 0; r < 4; r++) {
            int b = mb + r;
            float A = Xex[b * 2 * HID + 0 * HID + j];
            float B = Xex[b * 2 * HID + 1 * HID + j];
            float iv, fv, gv, ov;
            if (gp == 0) { iv = g0[b]; fv = g1[b]; gv = A; ov = B; }
            else         { gv = g0[b]; ov = g1[b]; iv = A; fv = B; }
            c[r] = sigf(fv) * c[r] + sigf(iv) * tanhf_fast(gv);
            float h = sigf(ov) * tanhf_fast(c[r]);
            Hw[b * HID + j] = h;
        }
        ((float4*)(sm + OFF_HS + wb * BPB * HID))[tid] = stg;
        __syncthreads();
    }

    // =================== output FC ===================
    const float* hfin = sm + OFF_HH;   // last write went to buffer 0 (t=511 -> wb=0)
    int w = tid >> 5, lane = tid & 31;
    if (w < BPB) {
        float s = 0.f;
#pragma unroll
        for (int m = 0; m < HID; m += 32)
            s += hfin[w * HID + lane + m] * __ldg(fcw + lane + m);
#pragma unroll
        for (int o = 16; o > 0; o >>= 1) s += __shfl_down_sync(0xffffffffu, s, o);
        if (lane == 0) out[bg0 + w] = s + __ldg(fcb);
    }
}

// ---------------- launch ----------------
extern "C" void kernel_launch(void* const* d_in, const int* in_sizes, int n_in,
                              void* d_out, int out_size) {
    const float* x    = (const float*)d_in[0];
    const float* wih0 = (const float*)d_in[1];
    const float* whh0 = (const float*)d_in[2];
    const float* bih0 = (const float*)d_in[3];
    const float* bhh0 = (const float*)d_in[4];
    const float* wih1 = (const float*)d_in[5];
    const float* whh1 = (const float*)d_in[6];
    const float* bih1 = (const float*)d_in[7];
    const float* bhh1 = (const float*)d_in[8];
    const float* fcw  = (const float*)d_in[9];
    const float* fcb  = (const float*)d_in[10];
    float* out = (float*)d_out;

    (void)in_sizes; (void)n_in; (void)out_size;

    cudaFuncSetAttribute(lstm_persistent,
                         cudaFuncAttributeMaxDynamicSharedMemorySize, SMEM_BYTES);

    pack_kernel<<<(GATES * HID + 255) / 256, 256>>>(whh0, whh1, wih1);
    lstm_persistent<<<NBLK, NTHR, SMEM_BYTES>>>(x, wih0, bih0, bhh0,
                                                bih1, bhh1, fcw, fcb, out);
}